// round 2
// baseline (speedup 1.0000x reference)
#include <cuda_runtime.h>
#include <cuda_bf16.h>
#include <math.h>

#define NN    50000
#define EE    800000
#define DIN   300
#define DH    96
#define DOUT  2
#define GG    64

// ---------------- scratch (device globals; no allocation allowed) -----------
__device__ float g_dis[NN];                 // deg -> deg_inv_sqrt (in place)
__device__ float g_h  [(size_t)NN * DH];    // transformed features (h1, then h2)
__device__ float g_agg[(size_t)NN * DH];    // aggregation buffer (layer1 then layer2)
__device__ float g_pool[GG * DH];
__device__ float g_cnt [GG];

// ---------------- degree ----------------------------------------------------
__global__ void k_deg_init() {
    int i = blockIdx.x * blockDim.x + threadIdx.x;
    if (i < NN) g_dis[i] = 1.0f;            // +1 self loop
}
__global__ void k_deg_count(const int* __restrict__ dst) {
    int e = blockIdx.x * blockDim.x + threadIdx.x;
    if (e < EE) atomicAdd(&g_dis[dst[e]], 1.0f);
}
__global__ void k_deg_finish() {            // rsqrt + zero pool/cnt
    int i = blockIdx.x * blockDim.x + threadIdx.x;
    if (i < NN) g_dis[i] = rsqrtf(g_dis[i]);
    if (i < GG * DH) g_pool[i] = 0.0f;
    if (i < GG)      g_cnt[i]  = 0.0f;
}

// ---------------- tiled SGEMM: out = in @ W  (BN = 96 = full width) ---------
// BM=64 rows/block, BK=16, 256 threads, 4x6 micro-tile per thread.
// Epilogue writes g_h = acc and g_agg = acc * dis^2 (self-loop init).
// IN_IS_AGG: read input from the device-global g_agg (layer-2 path) instead of
// the `in` kernel argument (device symbols must NOT be passed from host code).
// RELU_BIAS: input element is relu(in + bias[k]) (layer-2 path).
template <int K, bool RELU_BIAS, bool IN_IS_AGG>
__global__ void __launch_bounds__(256)
k_gemm(const float* __restrict__ in, const float* __restrict__ W,
       const float* __restrict__ bias)
{
    __shared__ float xs[16 * 68];       // [kk][row], pad 68 to dodge conflicts
    __shared__ float ws[16 * 96];       // [kk][col]
    __shared__ float bs[DH];

    const int tid = threadIdx.x;
    const int ty  = tid >> 4;           // 0..15 -> row group (4 rows)
    const int tx  = tid & 15;           // 0..15 -> col group (6 cols)
    const int r0  = blockIdx.x * 64;

    const float* __restrict__ src_in = IN_IS_AGG ? (const float*)g_agg : in;

    if (RELU_BIAS) { if (tid < DH) bs[tid] = bias[tid]; }

    float acc[4][6];
#pragma unroll
    for (int i = 0; i < 4; i++)
#pragma unroll
        for (int j = 0; j < 6; j++) acc[i][j] = 0.0f;

    const int nstage = (K + 15) / 16;
    for (int s = 0; s < nstage; s++) {
        const int k0 = s * 16;
        __syncthreads();
        // load x tile (64 x 16), transposed into xs[kk][row]
#pragma unroll
        for (int idx = tid; idx < 64 * 16; idx += 256) {
            int row = idx >> 4, kk = idx & 15;
            int gr = r0 + row, gk = k0 + kk;
            float v = 0.0f;
            if (gr < NN && gk < K) {
                v = src_in[(size_t)gr * K + gk];
                if (RELU_BIAS) v = fmaxf(v + bs[gk], 0.0f);
            }
            xs[kk * 68 + row] = v;
        }
        // load W tile (16 x 96)
#pragma unroll
        for (int idx = tid; idx < 16 * 96; idx += 256) {
            int kk = idx / 96, col = idx % 96;
            int gk = k0 + kk;
            ws[kk * 96 + col] = (gk < K) ? W[(size_t)gk * 96 + col] : 0.0f;
        }
        __syncthreads();
#pragma unroll
        for (int kk = 0; kk < 16; kk++) {
            float4 a4 = *reinterpret_cast<const float4*>(&xs[kk * 68 + ty * 4]);
            float a[4] = {a4.x, a4.y, a4.z, a4.w};
            float b[6];
#pragma unroll
            for (int j = 0; j < 6; j++) b[j] = ws[kk * 96 + tx * 6 + j];
#pragma unroll
            for (int i = 0; i < 4; i++)
#pragma unroll
                for (int j = 0; j < 6; j++) acc[i][j] = fmaf(a[i], b[j], acc[i][j]);
        }
    }
    __syncthreads();
    // epilogue
#pragma unroll
    for (int i = 0; i < 4; i++) {
        int r = r0 + ty * 4 + i;
        if (r >= NN) continue;
        float ds = g_dis[r];
        float d2 = ds * ds;
#pragma unroll
        for (int j = 0; j < 6; j++) {
            int c = tx * 6 + j;
            size_t o = (size_t)r * 96 + c;
            g_h[o]   = acc[i][j];
            g_agg[o] = acc[i][j] * d2;
        }
    }
}

// ---------------- edge scatter: agg[dst] += h[src] * dis[src]*dis[dst] ------
// block (24, 8): 24 float4-chunks per edge, 8 edges per block.
__global__ void __launch_bounds__(192)
k_scatter(const int* __restrict__ src, const int* __restrict__ dst)
{
    int e = blockIdx.x * 8 + threadIdx.y;
    if (e >= EE) return;
    int s = src[e], d = dst[e];
    float nrm = g_dis[s] * g_dis[d];
    int c = threadIdx.x * 4;
    float4 v = *reinterpret_cast<const float4*>(g_h + (size_t)s * 96 + c);
    float4 m = make_float4(v.x * nrm, v.y * nrm, v.z * nrm, v.w * nrm);
    float* p = g_agg + (size_t)d * 96 + c;
    asm volatile("red.global.add.v4.f32 [%0], {%1, %2, %3, %4};"
                 :: "l"(__cvta_generic_to_global(p)),
                    "f"(m.x), "f"(m.y), "f"(m.z), "f"(m.w) : "memory");
}

// ---------------- pooling: pool[g] += relu(agg2 + b2); cnt[g] += 1 ----------
// 96 threads/block (one per feature), 64 rows/block, run-length flushing.
__global__ void __launch_bounds__(96)
k_pool(const float* __restrict__ b2, const int* __restrict__ batch)
{
    int c  = threadIdx.x;
    int r0 = blockIdx.x * 64;
    int re = min(r0 + 64, NN);
    if (r0 >= NN) return;
    float bb = b2[c];
    float acc = 0.0f;
    int cur = batch[r0];
    int run = 0;
    for (int r = r0; r < re; r++) {
        int g = batch[r];
        if (g != cur) {
            atomicAdd(&g_pool[cur * DH + c], acc);
            if (c == 0) atomicAdd(&g_cnt[cur], (float)run);
            acc = 0.0f; run = 0; cur = g;
        }
        acc += fmaxf(g_agg[(size_t)r * 96 + c] + bb, 0.0f);
        run++;
    }
    atomicAdd(&g_pool[cur * DH + c], acc);
    if (c == 0) atomicAdd(&g_cnt[cur], (float)run);
}

// ---------------- head: out = (pool/cnt) @ Wfc + bfc -------------------------
__global__ void k_fc(const float* __restrict__ Wfc, const float* __restrict__ bfc,
                     float* __restrict__ out)
{
    int t = threadIdx.x;
    if (t >= GG * DOUT) return;
    int g = t >> 1, o = t & 1;
    float cn = fmaxf(g_cnt[g], 1.0f);
    float s = bfc[o];
    for (int c = 0; c < DH; c++)
        s += (g_pool[g * DH + c] / cn) * Wfc[c * DOUT + o];
    out[g * DOUT + o] = s;
}

// ---------------- launch -----------------------------------------------------
extern "C" void kernel_launch(void* const* d_in, const int* in_sizes, int n_in,
                              void* d_out, int out_size)
{
    const float* x    = (const float*)d_in[0];
    const float* W1   = (const float*)d_in[1];
    const float* b1   = (const float*)d_in[2];
    const float* W2   = (const float*)d_in[3];
    const float* b2   = (const float*)d_in[4];
    const float* Wfc  = (const float*)d_in[5];
    const float* bfc  = (const float*)d_in[6];
    const int*   src  = (const int*)d_in[7];
    const int*   dst  = (const int*)d_in[8];
    const int*   batch= (const int*)d_in[9];
    float* out = (float*)d_out;

    const int nb_n = (NN + 255) / 256;
    const int nb_e = (EE + 255) / 256;
    const int nb_g = (NN + 63) / 64;

    k_deg_init  <<<nb_n, 256>>>();
    k_deg_count <<<nb_e, 256>>>(dst);
    k_deg_finish<<<nb_n, 256>>>();

    // layer 1: h1 = x@W1; agg1 = h1*dis^2
    k_gemm<DIN, false, false><<<nb_g, 256>>>(x, W1, b1);
    k_scatter<<<(EE + 7) / 8, dim3(24, 8)>>>(src, dst);   // agg1 += msgs

    // layer 2: h2 = relu(agg1+b1)@W2; agg2 = h2*dis^2 (reads g_agg internally)
    k_gemm<DH, true, true><<<nb_g, 256>>>(nullptr, W2, b1);
    k_scatter<<<(EE + 7) / 8, dim3(24, 8)>>>(src, dst);   // agg2 += msgs

    k_pool<<<nb_g, 96>>>(b2, batch);
    k_fc  <<<1, 128>>>(Wfc, bfc, out);
}